// round 2
// baseline (speedup 1.0000x reference)
#include <cuda_runtime.h>
#include <math.h>

#define BZ 32
#define NP 576
#define WC 32
#define DD 256

// scratch (no cudaMalloc allowed)
__device__ float g_img_n[BZ * NP * DD];   // normalized image tokens
__device__ float g_con_n[BZ * WC * DD];   // normalized concept texts
__device__ float g_sim[BZ * BZ];          // sim matrix

// ---------------------------------------------------------------------------
// Normalize rows of length 256. One warp per row, 8 rows per 256-thread block.
// which==0 -> write g_img_n, which==1 -> write g_con_n
// ---------------------------------------------------------------------------
__global__ void norm_kernel(const float* __restrict__ in, int rows, int which) {
    int row  = blockIdx.x * (blockDim.x >> 5) + (threadIdx.x >> 5);
    int lane = threadIdx.x & 31;
    if (row >= rows) return;

    const float4* ip = reinterpret_cast<const float4*>(in) + (size_t)row * 64;
    float4 a = ip[lane];
    float4 b = ip[lane + 32];
    float s = a.x*a.x + a.y*a.y + a.z*a.z + a.w*a.w
            + b.x*b.x + b.y*b.y + b.z*b.z + b.w*b.w;
#pragma unroll
    for (int o = 16; o; o >>= 1) s += __shfl_xor_sync(0xffffffffu, s, o);

    float inv = 1.0f / fmaxf(sqrtf(s), 1e-12f);

    float* outb = which ? g_con_n : g_img_n;
    float4* op = reinterpret_cast<float4*>(outb) + (size_t)row * 64;
    a.x *= inv; a.y *= inv; a.z *= inv; a.w *= inv;
    b.x *= inv; b.y *= inv; b.z *= inv; b.w *= inv;
    op[lane]      = a;
    op[lane + 32] = b;
}

// ---------------------------------------------------------------------------
// Main kernel: one CTA per (m, c). Computes sim[m][c] =
//   (1/L_c) * sum_{w<L_c} max_n dot(img_n[m,n,:], con_n[c,w,:])
//
// smem layout:
//   con_s : [256][32] fp32 (con transposed, k-major) = 32 KB
//   img_s : [32][264] fp32 (32-patch tile, rows padded +8 floats) = 33.75 KB
//   red   : [32][33] fp32 max-reduction buffer = 4.125 KB
// Thread layout: tid = ty*8 + tx ; ty = patch row (0..31), tx = w-group (0..7)
// Each thread accumulates 4 concepts (w = 4*tx .. 4*tx+3) for its patch.
// Per k4 step: 1 img LDS.128 (broadcast x8) + 4 con LDS.128 (conflict-free)
// + 16 FFMA  -> FFMA-pipe bound.
// ---------------------------------------------------------------------------
#define SMEM_FLOATS (DD*WC + 32*264 + 32*33)

__global__ void __launch_bounds__(256, 3) sim_kernel(const int* __restrict__ lens) {
    extern __shared__ float sm[];
    float*  con_s = sm;                      // 8192 floats
    float4* con4  = reinterpret_cast<float4*>(con_s);
    float*  img_s = sm + DD * WC;            // 32*264 floats
    float4* img4  = reinterpret_cast<float4*>(img_s);
    float*  red   = img_s + 32 * 264;        // 32*33 floats

    const int m = blockIdx.x;
    const int c = blockIdx.y;
    const int tid = threadIdx.x;
    const int tx  = tid & 7;     // w-group
    const int ty  = tid >> 3;    // patch row within tile

    // load + transpose concepts for sample c: con_s[k*32 + w] = con_n[c][w][k]
    const float* conp = g_con_n + (size_t)c * WC * DD;
    for (int i = tid; i < WC * DD; i += 256) {
        int w = i >> 8;          // i / 256
        int k = i & 255;
        con_s[k * WC + w] = conp[i];
    }

    const float4* gimg = reinterpret_cast<const float4*>(g_img_n + (size_t)m * NP * DD);

    float4 mx = make_float4(-INFINITY, -INFINITY, -INFINITY, -INFINITY);

#pragma unroll 1
    for (int t = 0; t < NP / 32; t++) {
        __syncthreads();   // protect img_s (and con_s on first iter)

        // load 32 patch rows (32*256 floats = 2048 float4) cooperatively
#pragma unroll
        for (int j = 0; j < 8; j++) {
            int idx = tid + j * 256;      // float4 index within tile
            int r   = idx >> 6;           // row (64 float4 per row)
            int col = idx & 63;
            img4[r * 66 + col] = gimg[t * 2048 + idx];
        }
        __syncthreads();

        float4 acc = make_float4(0.f, 0.f, 0.f, 0.f);
#pragma unroll
        for (int k4 = 0; k4 < 64; k4++) {
            float4 a = img4[ty * 66 + k4];
            float4 b;
            b = con4[(k4 * 4 + 0) * 8 + tx];
            acc.x = fmaf(a.x, b.x, acc.x); acc.y = fmaf(a.x, b.y, acc.y);
            acc.z = fmaf(a.x, b.z, acc.z); acc.w = fmaf(a.x, b.w, acc.w);
            b = con4[(k4 * 4 + 1) * 8 + tx];
            acc.x = fmaf(a.y, b.x, acc.x); acc.y = fmaf(a.y, b.y, acc.y);
            acc.z = fmaf(a.y, b.z, acc.z); acc.w = fmaf(a.y, b.w, acc.w);
            b = con4[(k4 * 4 + 2) * 8 + tx];
            acc.x = fmaf(a.z, b.x, acc.x); acc.y = fmaf(a.z, b.y, acc.y);
            acc.z = fmaf(a.z, b.z, acc.z); acc.w = fmaf(a.z, b.w, acc.w);
            b = con4[(k4 * 4 + 3) * 8 + tx];
            acc.x = fmaf(a.w, b.x, acc.x); acc.y = fmaf(a.w, b.y, acc.y);
            acc.z = fmaf(a.w, b.z, acc.z); acc.w = fmaf(a.w, b.w, acc.w);
        }
        mx.x = fmaxf(mx.x, acc.x);
        mx.y = fmaxf(mx.y, acc.y);
        mx.z = fmaxf(mx.z, acc.z);
        mx.w = fmaxf(mx.w, acc.w);
    }

    __syncthreads();
    red[(tx * 4 + 0) * 33 + ty] = mx.x;
    red[(tx * 4 + 1) * 33 + ty] = mx.y;
    red[(tx * 4 + 2) * 33 + ty] = mx.z;
    red[(tx * 4 + 3) * 33 + ty] = mx.w;
    __syncthreads();

    if (tid < 32) {
        float v = -INFINITY;
#pragma unroll
        for (int r = 0; r < 32; r++) v = fmaxf(v, red[tid * 33 + r]);
        int L = lens[c];
        float val = (tid < L) ? v : 0.0f;
#pragma unroll
        for (int o = 16; o; o >>= 1) val += __shfl_xor_sync(0xffffffffu, val, o);
        if (tid == 0) g_sim[m * BZ + c] = val / (float)L;
    }
}

// ---------------------------------------------------------------------------
// Final loss: -mean(log_sigmoid(z * clip(t*sim + bias, -50, 50)))
// ---------------------------------------------------------------------------
__global__ void loss_kernel(const float* __restrict__ scale,
                            const float* __restrict__ bias,
                            float* __restrict__ out) {
    __shared__ float sred[256];
    int tid = threadIdx.x;

    float ls_clamped = fminf(fmaxf(scale[0], -10.0f), 10.0f);
    float t = expf(ls_clamped);
    float bb = bias[0];

    float s = 0.0f;
    for (int i = tid; i < BZ * BZ; i += 256) {
        int mm = i >> 5;
        int cc = i & 31;
        float logit = fminf(fmaxf(t * g_sim[i] + bb, -50.0f), 50.0f);
        float z = (mm == cc) ? 1.0f : -1.0f;
        float x = z * logit;
        // log_sigmoid(x) = min(x,0) - log1p(exp(-|x|))
        float lsg = fminf(x, 0.0f) - log1pf(expf(-fabsf(x)));
        s += lsg;
    }
    sred[tid] = s;
    __syncthreads();
    for (int o = 128; o; o >>= 1) {
        if (tid < o) sred[tid] += sred[tid + o];
        __syncthreads();
    }
    if (tid == 0) out[0] = -sred[0] / (float)(BZ * BZ);
}

// ---------------------------------------------------------------------------
extern "C" void kernel_launch(void* const* d_in, const int* in_sizes, int n_in,
                              void* d_out, int out_size) {
    // identify inputs by element count (robust to metadata ordering)
    const float* img = nullptr;
    const float* con = nullptr;
    const int*   len = nullptr;
    const float* scalars[2] = {nullptr, nullptr};
    int ns = 0;
    for (int i = 0; i < n_in; i++) {
        if (in_sizes[i] == BZ * NP * DD)       img = (const float*)d_in[i];
        else if (in_sizes[i] == BZ * WC * DD)  con = (const float*)d_in[i];
        else if (in_sizes[i] == BZ)            len = (const int*)d_in[i];
        else if (in_sizes[i] == 1 && ns < 2)   scalars[ns++] = (const float*)d_in[i];
    }
    const float* scale = scalars[0];  // logit_scale comes first in input order
    const float* bias  = scalars[1];

    // normalize
    norm_kernel<<<(BZ * NP + 7) / 8, 256>>>(img, BZ * NP, 0);
    norm_kernel<<<(BZ * WC + 7) / 8, 256>>>(con, BZ * WC, 1);

    // sim matrix
    size_t smem = SMEM_FLOATS * sizeof(float);
    cudaFuncSetAttribute(sim_kernel, cudaFuncAttributeMaxDynamicSharedMemorySize, (int)smem);
    dim3 grid(BZ, BZ);
    sim_kernel<<<grid, 256, smem>>>(len);

    // scalar loss
    loss_kernel<<<1, 256>>>(scale, bias, (float*)d_out);
}

// round 15
// speedup vs baseline: 4.8953x; 4.8953x over previous
#include <cuda_runtime.h>
#include <cuda_bf16.h>
#include <math.h>
#include <stdint.h>

#define BZ 32
#define NP 576            // 576 = 9 * 64  -> M-chunks of 64, no padding needed
#define WC 32
#define DD 256
#define KS 768            // split-bf16: 3 * 256

// ---------------- scratch (no cudaMalloc allowed) ----------------
__device__ __align__(16) __nv_bfloat16 g_img_s[BZ * NP * KS]; // (hi, hi, lo)
__device__ __align__(16) __nv_bfloat16 g_con_s[BZ * WC * KS]; // (hi, lo, hi)
__device__ float g_sim[BZ * BZ];

// ---------------- PTX helpers (all baseline sm_80+ — compile at sm_103) ----
__device__ __forceinline__ uint32_t smem_u32(const void* p) {
    uint32_t a;
    asm("{ .reg .u64 t; cvta.to.shared.u64 t, %1; cvt.u32.u64 %0, t; }" : "=r"(a) : "l"(p));
    return a;
}

#define SWZ(off) ((off) ^ (((off) >> 3) & 0x70))

#define CP16(dst, src) \
    asm volatile("cp.async.cg.shared.global [%0], [%1], 16;" :: "r"(dst), "l"(src))

#define LDSM4(r0, r1, r2, r3, addr) \
    asm volatile("ldmatrix.sync.aligned.m8n8.x4.shared.b16 {%0,%1,%2,%3}, [%4];" \
                 : "=r"(r0), "=r"(r1), "=r"(r2), "=r"(r3) : "r"(addr))

#define MMA(c, a0, a1, a2, a3, b0, b1) \
    asm volatile("mma.sync.aligned.m16n8k16.row.col.f32.bf16.bf16.f32 " \
                 "{%0,%1,%2,%3},{%4,%5,%6,%7},{%8,%9},{%0,%1,%2,%3};" \
                 : "+f"((c)[0]), "+f"((c)[1]), "+f"((c)[2]), "+f"((c)[3]) \
                 : "r"(a0), "r"(a1), "r"(a2), "r"(a3), "r"(b0), "r"(b1))

// ---------------- normalize + split into bf16 hi/lo ----------------
__device__ __forceinline__ void split_store(__nv_bfloat16* p, int k, float4 v, float inv,
                                            int lo_off, int hi2_off) {
    float x0 = v.x * inv, x1 = v.y * inv, x2 = v.z * inv, x3 = v.w * inv;
    __nv_bfloat16 h0 = __float2bfloat16(x0), h1 = __float2bfloat16(x1);
    __nv_bfloat16 h2 = __float2bfloat16(x2), h3 = __float2bfloat16(x3);
    __nv_bfloat16 l0 = __float2bfloat16(x0 - __bfloat162float(h0));
    __nv_bfloat16 l1 = __float2bfloat16(x1 - __bfloat162float(h1));
    __nv_bfloat16 l2 = __float2bfloat16(x2 - __bfloat162float(h2));
    __nv_bfloat16 l3 = __float2bfloat16(x3 - __bfloat162float(h3));
    __nv_bfloat162* d;
    d = (__nv_bfloat162*)(p + k);
    d[0] = __nv_bfloat162(h0, h1); d[1] = __nv_bfloat162(h2, h3);
    d = (__nv_bfloat162*)(p + k + hi2_off);
    d[0] = __nv_bfloat162(h0, h1); d[1] = __nv_bfloat162(h2, h3);
    d = (__nv_bfloat162*)(p + k + lo_off);
    d[0] = __nv_bfloat162(l0, l1); d[1] = __nv_bfloat162(l2, l3);
}

__global__ void norm_split_img(const float* __restrict__ in) {
    int row  = blockIdx.x * 8 + (threadIdx.x >> 5);
    int lane = threadIdx.x & 31;
    if (row >= BZ * NP) return;
    const float4* ip = (const float4*)in + (size_t)row * 64;
    float4 a = ip[lane], b = ip[lane + 32];
    float s = a.x*a.x + a.y*a.y + a.z*a.z + a.w*a.w
            + b.x*b.x + b.y*b.y + b.z*b.z + b.w*b.w;
#pragma unroll
    for (int o = 16; o; o >>= 1) s += __shfl_xor_sync(0xffffffffu, s, o);
    float inv = 1.0f / fmaxf(sqrtf(s), 1e-12f);
    __nv_bfloat16* go = g_img_s + (size_t)row * KS;
    split_store(go, 4 * lane, a, inv, 512, 256);        // img: (hi, hi, lo)
    split_store(go, 128 + 4 * lane, b, inv, 512, 256);
}

__global__ void norm_split_con(const float* __restrict__ in) {
    int row  = blockIdx.x * 8 + (threadIdx.x >> 5);
    int lane = threadIdx.x & 31;
    if (row >= BZ * WC) return;
    const float4* ip = (const float4*)in + (size_t)row * 64;
    float4 a = ip[lane], b = ip[lane + 32];
    float s = a.x*a.x + a.y*a.y + a.z*a.z + a.w*a.w
            + b.x*b.x + b.y*b.y + b.z*b.z + b.w*b.w;
#pragma unroll
    for (int o = 16; o; o >>= 1) s += __shfl_xor_sync(0xffffffffu, s, o);
    float inv = 1.0f / fmaxf(sqrtf(s), 1e-12f);
    __nv_bfloat16* go = g_con_s + (size_t)row * KS;
    split_store(go, 4 * lane, a, inv, 256, 512);        // con: (hi, lo, hi)
    split_store(go, 128 + 4 * lane, b, inv, 256, 512);
}

// ---------------- mma.sync GEMM + column-max + masked mean ----------------
// CTA = (m, ct of 4 samples = 128 concept rows).
// smem: B resident: 12 K-chunks x [128 rows x 128B, SW128]   = 196608 B
//       A chunks   : 2 x [64 rows x 128B, SW128] double-buf  =  16384 B
// 8 warps = 4(M) x 2(N); warp tile 16 patches x 64 concepts.
// Per-concept max kept in 16 registers/thread across all 9 M-chunks.
#define SM_B   0
#define SM_A0  196608
#define SM_A1  204800
#define SMEM_BYTES 212992

#define LOAD_A(mc_, kc_, buf_off) do { \
    _Pragma("unroll") \
    for (int t_ = 0; t_ < 2; t_++) { \
        int idx_ = tid + t_ * 256; \
        int r_ = idx_ >> 3, i16_ = idx_ & 7; \
        const char* src_ = (const char*)(g_img_s + (size_t)(m * NP + (mc_) * 64 + r_) * KS) \
                         + (kc_) * 128 + i16_ * 16; \
        uint32_t off_ = (uint32_t)(r_ * 128 + i16_ * 16); \
        CP16(sb + (buf_off) + SWZ(off_), src_); \
    } \
} while (0)

__global__ void __launch_bounds__(256, 1) sim_mma_kernel(const int* __restrict__ lens) {
    extern __shared__ char smem[];
    const uint32_t sb = smem_u32(smem);
    const int tid = threadIdx.x, wid = tid >> 5, lane = tid & 31;
    const int m = blockIdx.x, ct = blockIdx.y;
    const int wm = wid >> 1, wn = wid & 1;

    // -------- B resident load (cp.async, group 0) --------
#pragma unroll 4
    for (int t = 0; t < 48; t++) {
        int idx = tid + t * 256;
        int kc = idx >> 10, rem = idx & 1023, r = rem >> 3, i16 = rem & 7;
        const char* src = (const char*)(g_con_s + (size_t)(ct * 128 + r) * KS)
                        + kc * 128 + i16 * 16;
        uint32_t off = (uint32_t)(r * 128 + i16 * 16);
        CP16(sb + SM_B + kc * 16384 + SWZ(off), src);
    }
    LOAD_A(0, 0, SM_A0);
    asm volatile("cp.async.commit_group;" ::: "memory");

    float acc[8][4];
    float mx[16];
#pragma unroll
    for (int f = 0; f < 8; f++) { acc[f][0] = acc[f][1] = acc[f][2] = acc[f][3] = 0.f; }
#pragma unroll
    for (int i = 0; i < 16; i++) mx[i] = -INFINITY;

    // per-lane ldmatrix address components (within a chunk)
    const int arow = (wm << 4) + (lane & 15);           // A row within 64-row chunk
    const int acb  = (lane >> 4) << 4;                   // 0 / +16B (k vs k+8)
    const int brow = (wn << 6) + (lane & 7) + ((lane >> 4) << 3);  // B row base
    const int bcb  = ((lane >> 3) & 1) << 4;

    int mc = 0, kc = 0;
#pragma unroll 1
    for (int q = 0; q < 108; q++) {
        if (q + 1 < 108) {
            int nkc = kc + 1, nmc = mc;
            if (nkc == 12) { nkc = 0; nmc = mc + 1; }
            LOAD_A(nmc, nkc, ((q + 1) & 1) ? SM_A1 : SM_A0);
            asm volatile("cp.async.commit_group;" ::: "memory");
            asm volatile("cp.async.wait_group 1;" ::: "memory");
        } else {
            asm volatile("cp.async.wait_group 0;" ::: "memory");
        }
        __syncthreads();

        const uint32_t abase = sb + ((q & 1) ? SM_A1 : SM_A0);
        const uint32_t bbase = sb + SM_B + kc * 16384;

#pragma unroll
        for (int k16 = 0; k16 < 4; k16++) {
            uint32_t aoff = (uint32_t)(arow * 128 + acb + k16 * 32);
            uint32_t A0, A1, A2, A3;
            LDSM4(A0, A1, A2, A3, abase + SWZ(aoff));
#pragma unroll
            for (int f4 = 0; f4 < 4; f4++) {
                uint32_t boff = (uint32_t)((brow + f4 * 16) * 128 + bcb + k16 * 32);
                uint32_t B0, B1, B2, B3;
                LDSM4(B0, B1, B2, B3, bbase + SWZ(boff));
                MMA(acc[2 * f4],     A0, A1, A2, A3, B0, B1);
                MMA(acc[2 * f4 + 1], A0, A1, A2, A3, B2, B3);
            }
        }

        if (kc == 11) {   // end of K for this M-chunk: fold C into running max
#pragma unroll
            for (int f = 0; f < 8; f++) {
                mx[2 * f]     = fmaxf(mx[2 * f],     fmaxf(acc[f][0], acc[f][2]));
                mx[2 * f + 1] = fmaxf(mx[2 * f + 1], fmaxf(acc[f][1], acc[f][3]));
                acc[f][0] = acc[f][1] = acc[f][2] = acc[f][3] = 0.f;
            }
        }
        __syncthreads();   // protect A buffer (q+1)&1 before next-iter cp.async
        kc++; if (kc == 12) { kc = 0; mc++; }
    }

    // -------- reduce max over the 16 patch rows held by this warp --------
#pragma unroll
    for (int i = 0; i < 16; i++) {
        float v = mx[i];
        v = fmaxf(v, __shfl_xor_sync(0xffffffffu, v, 4));
        v = fmaxf(v, __shfl_xor_sync(0xffffffffu, v, 8));
        v = fmaxf(v, __shfl_xor_sync(0xffffffffu, v, 16));
        mx[i] = v;
    }

    float* red = (float*)smem;   // A/B smem dead now (last loop iter ended with sync)
    if ((lane >> 2) == 0) {      // lanes 0-3 hold canonical column maxes
#pragma unroll
        for (int f = 0; f < 8; f++) {
            red[wid * 64 + f * 8 + (lane & 3) * 2 + 0] = mx[2 * f];
            red[wid * 64 + f * 8 + (lane & 3) * 2 + 1] = mx[2 * f + 1];
        }
    }
    __syncthreads();

    // -------- combine 4 M-warps, masked mean per sample --------
    if (tid < 128) {
        int n = tid;                       // concept row within ct tile
        int nh = n >> 6, nn = n & 63;
        float v = fmaxf(fmaxf(red[(nh + 0) * 64 + nn], red[(nh + 2) * 64 + nn]),
                        fmaxf(red[(nh + 4) * 64 + nn], red[(nh + 6) * 64 + nn]));
        int c = ct * 4 + (n >> 5);
        int w = n & 31;
        int L = lens[c];
        float val = (w < L) ? v : 0.0f;
#pragma unroll
        for (int o = 16; o; o >>= 1) val += __shfl_xor_sync(0xffffffffu, val, o);
        if (w == 0) g_sim[m * BZ + c] = val / (float)L;
    }
}

// ---------------- final loss ----------------
__global__ void loss_kernel(const float* __restrict__ scale,
                            const float* __restrict__ bias,
                            float* __restrict__ out) {
    __shared__ float sred[256];
    int tid = threadIdx.x;
    float t = expf(fminf(fmaxf(scale[0], -10.0f), 10.0f));
    float bb = bias[0];
    float s = 0.0f;
    for (int i = tid; i < BZ * BZ; i += 256) {
        int mm = i >> 5, cc = i & 31;
        float logit = fminf(fmaxf(t * g_sim[i] + bb, -50.0f), 50.0f);
        float x = ((mm == cc) ? 1.0f : -1.0f) * logit;
        s += fminf(x, 0.0f) - log1pf(expf(-fabsf(x)));
    }
    sred[tid] = s;
    __syncthreads();
    for (int o = 128; o; o >>= 1) {
        if (tid < o) sred[tid] += sred[tid + o];
        __syncthreads();
    }
    if (tid == 0) out[0] = -sred[0] / (float)(BZ * BZ);
}

// ---------------------------------------------------------------------------
extern "C" void kernel_launch(void* const* d_in, const int* in_sizes, int n_in,
                              void* d_out, int out_size) {
    const float* img = nullptr;
    const float* con = nullptr;
    const int*   len = nullptr;
    const float* scalars[2] = {nullptr, nullptr};
    int ns = 0;
    for (int i = 0; i < n_in; i++) {
        if (in_sizes[i] == BZ * NP * DD)       img = (const float*)d_in[i];
        else if (in_sizes[i] == BZ * WC * DD)  con = (const float*)d_in[i];
        else if (in_sizes[i] == BZ)            len = (const int*)d_in[i];
        else if (in_sizes[i] == 1 && ns < 2)   scalars[ns++] = (const float*)d_in[i];
    }
    const float* scale = scalars[0];
    const float* bias  = scalars[1];

    norm_split_img<<<(BZ * NP + 7) / 8, 256>>>(img);
    norm_split_con<<<(BZ * WC + 7) / 8, 256>>>(con);

    cudaFuncSetAttribute(sim_mma_kernel, cudaFuncAttributeMaxDynamicSharedMemorySize, SMEM_BYTES);
    dim3 grid(BZ, BZ / 4);
    sim_mma_kernel<<<grid, 256, SMEM_BYTES>>>(len);

    loss_kernel<<<1, 256>>>(scale, bias, (float*)d_out);
}